// round 1
// baseline (speedup 1.0000x reference)
#include <cuda_runtime.h>
#include <math.h>

// Problem constants
#define L_SEQ 2048
#define NB    4
#define EMB   1024
#define INNER 1024
#define H     16
#define DHEAD 64
#define BATCH (NB * H)          // 64 attention batches
#define M_ROWS (L_SEQ * NB)     // 8192 token rows
#define QSCALE 0.125f

// Scratch (device globals — no allocation allowed)
__device__ float g_Q[(size_t)BATCH * L_SEQ * DHEAD];   // 32 MB, pre-scaled by QSCALE
__device__ float g_K[(size_t)BATCH * L_SEQ * DHEAD];   // 32 MB
__device__ float g_V[(size_t)BATCH * L_SEQ * DHEAD];   // 32 MB
__device__ float g_O[(size_t)M_ROWS * INNER];          // 32 MB, (L*N, inner) layout

// ---------------------------------------------------------------------------
// Kernel 1: QKV projection GEMM with fused de-interleave epilogue.
// C[m][f] = sum_k X[m][k] * W[f][k] + bias[f]; f = 3*i + s,
// i = head*64+dd, m = l*NB+n. Writes g_Q (scaled), g_K, g_V in
// [b = n*16+head][l][dd] layout.
// Tiles: 64x64x16, 256 threads, 4x4 per-thread micro-tile.
// ---------------------------------------------------------------------------
__global__ __launch_bounds__(256) void qkv_gemm_kernel(
    const float* __restrict__ X, const float* __restrict__ W,
    const float* __restrict__ bias)
{
    __shared__ float As[16][64];   // [k][m] transposed
    __shared__ float Bs[16][64];   // [k][f] transposed

    const int tx = threadIdx.x & 15;
    const int ty = threadIdx.x >> 4;
    const int bm = blockIdx.x * 64;
    const int bn = blockIdx.y * 64;

    const int lr = threadIdx.x >> 2;        // 0..63 row within tile
    const int lc = (threadIdx.x & 3) * 4;   // 0,4,8,12 col group

    float acc[4][4] = {};

    for (int k0 = 0; k0 < EMB; k0 += 16) {
        float4 a = *reinterpret_cast<const float4*>(&X[(size_t)(bm + lr) * EMB + k0 + lc]);
        float4 b = *reinterpret_cast<const float4*>(&W[(size_t)(bn + lr) * EMB + k0 + lc]);
        As[lc + 0][lr] = a.x; As[lc + 1][lr] = a.y; As[lc + 2][lr] = a.z; As[lc + 3][lr] = a.w;
        Bs[lc + 0][lr] = b.x; Bs[lc + 1][lr] = b.y; Bs[lc + 2][lr] = b.z; Bs[lc + 3][lr] = b.w;
        __syncthreads();

#pragma unroll
        for (int kk = 0; kk < 16; ++kk) {
            float4 av4 = *reinterpret_cast<const float4*>(&As[kk][ty * 4]);
            float4 bv4 = *reinterpret_cast<const float4*>(&Bs[kk][tx * 4]);
            float av[4] = {av4.x, av4.y, av4.z, av4.w};
            float bv[4] = {bv4.x, bv4.y, bv4.z, bv4.w};
#pragma unroll
            for (int i = 0; i < 4; ++i)
#pragma unroll
                for (int j = 0; j < 4; ++j)
                    acc[i][j] = fmaf(av[i], bv[j], acc[i][j]);
        }
        __syncthreads();
    }

    // Epilogue: bias + de-interleave scatter into Q/K/V
#pragma unroll
    for (int i = 0; i < 4; ++i) {
        const int m = bm + ty * 4 + i;
        const int l = m >> 2;          // m / NB
        const int n = m & 3;           // m % NB
#pragma unroll
        for (int j = 0; j < 4; ++j) {
            const int f = bn + tx * 4 + j;
            float v = acc[i][j] + bias[f];
            const int ii = f / 3;
            const int s  = f - ii * 3;
            const int head = ii >> 6;        // / 64
            const int dd   = ii & 63;
            const int b = n * H + head;
            const size_t off = ((size_t)b * L_SEQ + l) * DHEAD + dd;
            if (s == 0)      g_Q[off] = v * QSCALE;
            else if (s == 1) g_K[off] = v;
            else             g_V[off] = v;
        }
    }
}

// ---------------------------------------------------------------------------
// Kernel 2: flash attention. One block = (head-batch b, 64-row query tile).
// Dynamic smem: Qs[64][64] (dd-major), Ks[64][64] (dd-major),
//               Vs[64][64] (key-major), Pt[64][64] (key-major P^T). 64 KB.
// ---------------------------------------------------------------------------
__device__ __forceinline__ float redmax16(float v) {
    v = fmaxf(v, __shfl_xor_sync(0xffffffffu, v, 1));
    v = fmaxf(v, __shfl_xor_sync(0xffffffffu, v, 2));
    v = fmaxf(v, __shfl_xor_sync(0xffffffffu, v, 4));
    v = fmaxf(v, __shfl_xor_sync(0xffffffffu, v, 8));
    return v;
}
__device__ __forceinline__ float redsum16(float v) {
    v += __shfl_xor_sync(0xffffffffu, v, 1);
    v += __shfl_xor_sync(0xffffffffu, v, 2);
    v += __shfl_xor_sync(0xffffffffu, v, 4);
    v += __shfl_xor_sync(0xffffffffu, v, 8);
    return v;
}

#define ATTN_SMEM (4 * 64 * 64 * 4)  // 65536 bytes

__global__ __launch_bounds__(256) void attn_kernel()
{
    extern __shared__ float smem[];
    float* Qs = smem;               // [dd][r]   : Qs[dd*64 + r]
    float* Ks = smem + 4096;        // [dd][c]   : Ks[dd*64 + c]
    float* Vs = smem + 8192;        // [j][dd]   : Vs[j*64 + dd]
    float* Pt = smem + 12288;       // [j][r]    : Pt[j*64 + r]

    const int b  = blockIdx.y;      // 0..63
    const int qt = blockIdx.x;      // 0..31

    const int tx = threadIdx.x & 15;
    const int ty = threadIdx.x >> 4;
    const int lr = threadIdx.x >> 2;       // 0..63
    const int c0 = (threadIdx.x & 3) * 4;  // 0,4,8,12

    const float* Qg = g_Q + ((size_t)b * L_SEQ + qt * 64) * DHEAD;

    // Load Q tile transposed (dd-major)
#pragma unroll
    for (int it = 0; it < 4; ++it) {
        const int c = c0 + it * 16;
        float4 q = *reinterpret_cast<const float4*>(&Qg[lr * DHEAD + c]);
        Qs[(c + 0) * 64 + lr] = q.x; Qs[(c + 1) * 64 + lr] = q.y;
        Qs[(c + 2) * 64 + lr] = q.z; Qs[(c + 3) * 64 + lr] = q.w;
    }

    float m_run[4] = {-INFINITY, -INFINITY, -INFINITY, -INFINITY};
    float l_run[4] = {0.f, 0.f, 0.f, 0.f};
    float acc[4][4] = {};

    for (int kt = 0; kt < L_SEQ / 64; ++kt) {
        const float* Kg = g_K + ((size_t)b * L_SEQ + kt * 64) * DHEAD;
        const float* Vg = g_V + ((size_t)b * L_SEQ + kt * 64) * DHEAD;
#pragma unroll
        for (int it = 0; it < 4; ++it) {
            const int c = c0 + it * 16;
            float4 k4 = *reinterpret_cast<const float4*>(&Kg[lr * DHEAD + c]);
            Ks[(c + 0) * 64 + lr] = k4.x; Ks[(c + 1) * 64 + lr] = k4.y;
            Ks[(c + 2) * 64 + lr] = k4.z; Ks[(c + 3) * 64 + lr] = k4.w;
            float4 v4 = *reinterpret_cast<const float4*>(&Vg[lr * DHEAD + c]);
            *reinterpret_cast<float4*>(&Vs[lr * 64 + c]) = v4;
        }
        __syncthreads();

        // S = (Q*scale) @ K^T, 4x4 per thread
        float s[4][4] = {};
#pragma unroll
        for (int dd = 0; dd < 64; ++dd) {
            float4 qv4 = *reinterpret_cast<const float4*>(&Qs[dd * 64 + ty * 4]);
            float4 kv4 = *reinterpret_cast<const float4*>(&Ks[dd * 64 + tx * 4]);
            float qv[4] = {qv4.x, qv4.y, qv4.z, qv4.w};
            float kv[4] = {kv4.x, kv4.y, kv4.z, kv4.w};
#pragma unroll
            for (int i = 0; i < 4; ++i)
#pragma unroll
                for (int j = 0; j < 4; ++j)
                    s[i][j] = fmaf(qv[i], kv[j], s[i][j]);
        }

        // Online softmax update
#pragma unroll
        for (int i = 0; i < 4; ++i) {
            float mx = fmaxf(fmaxf(s[i][0], s[i][1]), fmaxf(s[i][2], s[i][3]));
            mx = redmax16(mx);
            const float newm = fmaxf(m_run[i], mx);
            const float corr = __expf(m_run[i] - newm);
            m_run[i] = newm;
            float rs = 0.f;
#pragma unroll
            for (int j = 0; j < 4; ++j) {
                const float p = __expf(s[i][j] - newm);
                s[i][j] = p;
                rs += p;
            }
            rs = redsum16(rs);
            l_run[i] = l_run[i] * corr + rs;
#pragma unroll
            for (int j = 0; j < 4; ++j) acc[i][j] *= corr;
        }

        // Store P transposed: Pt[key][row]
#pragma unroll
        for (int i = 0; i < 4; ++i)
#pragma unroll
            for (int j = 0; j < 4; ++j)
                Pt[(tx * 4 + j) * 64 + (ty * 4 + i)] = s[i][j];
        __syncthreads();

        // O += P @ V
#pragma unroll
        for (int j = 0; j < 64; ++j) {
            float4 pv4 = *reinterpret_cast<const float4*>(&Pt[j * 64 + ty * 4]);
            float4 vv4 = *reinterpret_cast<const float4*>(&Vs[j * 64 + tx * 4]);
            float pv[4] = {pv4.x, pv4.y, pv4.z, pv4.w};
            float vv[4] = {vv4.x, vv4.y, vv4.z, vv4.w};
#pragma unroll
            for (int i = 0; i < 4; ++i)
#pragma unroll
                for (int jj = 0; jj < 4; ++jj)
                    acc[i][jj] = fmaf(pv[i], vv[jj], acc[i][jj]);
        }
        __syncthreads();
    }

    // Epilogue: normalize and scatter to (L*N, inner) layout
    const int n    = b >> 4;   // b / H
    const int head = b & 15;   // b % H
#pragma unroll
    for (int i = 0; i < 4; ++i) {
        const float inv = 1.0f / l_run[i];
        const int lg = qt * 64 + ty * 4 + i;
        const size_t base = ((size_t)lg * NB + n) * INNER + head * DHEAD + tx * 4;
        float4 o;
        o.x = acc[i][0] * inv; o.y = acc[i][1] * inv;
        o.z = acc[i][2] * inv; o.w = acc[i][3] * inv;
        *reinterpret_cast<float4*>(&g_O[base]) = o;
    }
}

// ---------------------------------------------------------------------------
// Kernel 3: output projection GEMM.
// out[m][e] = sum_i g_O[m][i] * Wo[e][i] + bo[e]
// ---------------------------------------------------------------------------
__global__ __launch_bounds__(256) void out_gemm_kernel(
    float* __restrict__ out, const float* __restrict__ Wo,
    const float* __restrict__ bo)
{
    __shared__ float As[16][64];
    __shared__ float Bs[16][64];

    const int tx = threadIdx.x & 15;
    const int ty = threadIdx.x >> 4;
    const int bm = blockIdx.x * 64;
    const int bn = blockIdx.y * 64;

    const int lr = threadIdx.x >> 2;
    const int lc = (threadIdx.x & 3) * 4;

    float acc[4][4] = {};

    for (int k0 = 0; k0 < INNER; k0 += 16) {
        float4 a = *reinterpret_cast<const float4*>(&g_O[(size_t)(bm + lr) * INNER + k0 + lc]);
        float4 b = *reinterpret_cast<const float4*>(&Wo[(size_t)(bn + lr) * INNER + k0 + lc]);
        As[lc + 0][lr] = a.x; As[lc + 1][lr] = a.y; As[lc + 2][lr] = a.z; As[lc + 3][lr] = a.w;
        Bs[lc + 0][lr] = b.x; Bs[lc + 1][lr] = b.y; Bs[lc + 2][lr] = b.z; Bs[lc + 3][lr] = b.w;
        __syncthreads();

#pragma unroll
        for (int kk = 0; kk < 16; ++kk) {
            float4 av4 = *reinterpret_cast<const float4*>(&As[kk][ty * 4]);
            float4 bv4 = *reinterpret_cast<const float4*>(&Bs[kk][tx * 4]);
            float av[4] = {av4.x, av4.y, av4.z, av4.w};
            float bv[4] = {bv4.x, bv4.y, bv4.z, bv4.w};
#pragma unroll
            for (int i = 0; i < 4; ++i)
#pragma unroll
                for (int j = 0; j < 4; ++j)
                    acc[i][j] = fmaf(av[i], bv[j], acc[i][j]);
        }
        __syncthreads();
    }

#pragma unroll
    for (int i = 0; i < 4; ++i) {
        const int m = bm + ty * 4 + i;
        const int e0 = bn + tx * 4;
        float4 o;
        o.x = acc[i][0] + bo[e0 + 0];
        o.y = acc[i][1] + bo[e0 + 1];
        o.z = acc[i][2] + bo[e0 + 2];
        o.w = acc[i][3] + bo[e0 + 3];
        *reinterpret_cast<float4*>(&out[(size_t)m * EMB + e0]) = o;
    }
}

// ---------------------------------------------------------------------------
extern "C" void kernel_launch(void* const* d_in, const int* in_sizes, int n_in,
                              void* d_out, int out_size)
{
    const float* query    = (const float*)d_in[0];  // (L, N, E)
    const float* qkv_proj = (const float*)d_in[1];  // (3*inner, E)
    const float* qkv_bias = (const float*)d_in[2];  // (3*inner,)
    const float* out_proj = (const float*)d_in[3];  // (E, inner)
    const float* out_bias = (const float*)d_in[4];  // (E,)
    float* out = (float*)d_out;                     // (L, N, E)

    static bool attr_set = false;
    if (!attr_set) {
        cudaFuncSetAttribute(attn_kernel,
                             cudaFuncAttributeMaxDynamicSharedMemorySize, ATTN_SMEM);
        attr_set = true;
    }

    dim3 g1(M_ROWS / 64, (3 * INNER) / 64);
    qkv_gemm_kernel<<<g1, 256>>>(query, qkv_proj, qkv_bias);

    dim3 g2(L_SEQ / 64, BATCH);
    attn_kernel<<<g2, 256, ATTN_SMEM>>>();

    dim3 g3(M_ROWS / 64, EMB / 64);
    out_gemm_kernel<<<g3, 256>>>(out, out_proj, out_bias);
}

// round 3
// speedup vs baseline: 1.5006x; 1.5006x over previous
#include <cuda_runtime.h>
#include <cuda_bf16.h>
#include <math.h>
#include <stdint.h>

// ---------------------------------------------------------------------------
// Problem constants
// ---------------------------------------------------------------------------
#define L_SEQ 2048
#define NB    4
#define EMB   1024
#define INNER 1024
#define H     16
#define DHEAD 64
#define BATCH (NB * H)          // 64
#define M_ROWS (L_SEQ * NB)     // 8192
#define QSCALE 0.125f

// ---------------------------------------------------------------------------
// Device-global scratch (no allocation allowed)
// ---------------------------------------------------------------------------
__device__ float g_Q[(size_t)BATCH * L_SEQ * DHEAD];
__device__ float g_K[(size_t)BATCH * L_SEQ * DHEAD];
__device__ float g_V[(size_t)BATCH * L_SEQ * DHEAD];

__device__ __nv_bfloat16 gXhi[(size_t)M_ROWS * EMB];
__device__ __nv_bfloat16 gXlo[(size_t)M_ROWS * EMB];
__device__ __nv_bfloat16 gW1hi[(size_t)3 * INNER * EMB];
__device__ __nv_bfloat16 gW1lo[(size_t)3 * INNER * EMB];
__device__ __nv_bfloat16 gW2hi[(size_t)EMB * INNER];
__device__ __nv_bfloat16 gW2lo[(size_t)EMB * INNER];
__device__ __nv_bfloat16 gOhi[(size_t)M_ROWS * INNER];
__device__ __nv_bfloat16 gOlo[(size_t)M_ROWS * INNER];

// ---------------------------------------------------------------------------
// warp mma helper: m16n8k16 row.col f32 += bf16 * bf16
// ---------------------------------------------------------------------------
__device__ __forceinline__ void mma16816(float* d, const uint32_t* a, const uint32_t* b)
{
    asm volatile(
        "mma.sync.aligned.m16n8k16.row.col.f32.bf16.bf16.f32 "
        "{%0,%1,%2,%3}, {%4,%5,%6,%7}, {%8,%9}, {%0,%1,%2,%3};"
        : "+f"(d[0]), "+f"(d[1]), "+f"(d[2]), "+f"(d[3])
        : "r"(a[0]), "r"(a[1]), "r"(a[2]), "r"(a[3]), "r"(b[0]), "r"(b[1]));
}

// ---------------------------------------------------------------------------
// Pre-pass: fp32 -> bf16 hi/lo split
// ---------------------------------------------------------------------------
template<int WHICH>
__global__ __launch_bounds__(256) void convert_kernel(const float* __restrict__ src, int n4)
{
    __nv_bfloat16* hi = (WHICH == 0) ? gXhi : (WHICH == 1) ? gW1hi : gW2hi;
    __nv_bfloat16* lo = (WHICH == 0) ? gXlo : (WHICH == 1) ? gW1lo : gW2lo;
    for (int i = blockIdx.x * blockDim.x + threadIdx.x; i < n4;
         i += gridDim.x * blockDim.x) {
        float4 v = reinterpret_cast<const float4*>(src)[i];
        float f[4] = {v.x, v.y, v.z, v.w};
        unsigned short hs[4], ls[4];
#pragma unroll
        for (int k = 0; k < 4; ++k) {
            __nv_bfloat16 h = __float2bfloat16(f[k]);
            __nv_bfloat16 l = __float2bfloat16(f[k] - __bfloat162float(h));
            hs[k] = __bfloat16_as_ushort(h);
            ls[k] = __bfloat16_as_ushort(l);
        }
        uint2 uh, ul;
        uh.x = (uint32_t)hs[0] | ((uint32_t)hs[1] << 16);
        uh.y = (uint32_t)hs[2] | ((uint32_t)hs[3] << 16);
        ul.x = (uint32_t)ls[0] | ((uint32_t)ls[1] << 16);
        ul.y = (uint32_t)ls[2] | ((uint32_t)ls[3] << 16);
        reinterpret_cast<uint2*>(hi)[i] = uh;
        reinterpret_cast<uint2*>(lo)[i] = ul;
    }
}

// ---------------------------------------------------------------------------
// Split-bf16 warp-MMA GEMM.  C[m][f] = sum_k A[m][k]*B[f][k] + bias[f]
// MODE 0: A = X, B = qkv_proj; epilogue de-interleaves into g_Q/g_K/g_V.
// MODE 1: A = attn output, B = out_proj; epilogue writes d_out.
// Block tile 128x128x64, 256 threads = 8 warps (4m x 2n), warp tile 32x64.
// ---------------------------------------------------------------------------
#define SMEM_PITCH 72   // bf16 elements per smem row (banks: 36 words ≡ 4 mod 32)
#define SMEM_ARR (128 * SMEM_PITCH)
#define GEMM_SMEM (4 * SMEM_ARR * 2)   // 73728 bytes

template<int MODE>
__global__ __launch_bounds__(256) void mma_gemm(const float* __restrict__ bias,
                                                float* __restrict__ outp)
{
    extern __shared__ __nv_bfloat16 sm[];
    __nv_bfloat16* sAh = sm;
    __nv_bfloat16* sAl = sm + SMEM_ARR;
    __nv_bfloat16* sBh = sm + 2 * SMEM_ARR;
    __nv_bfloat16* sBl = sm + 3 * SMEM_ARR;

    const int tid = threadIdx.x;
    const int wid = tid >> 5;
    const int lane = tid & 31;
    const int g   = lane >> 2;    // group id 0..7
    const int tig = lane & 3;     // thread in group
    const int wm = wid >> 1;      // warp m 0..3
    const int wn = wid & 1;       // warp n 0..1
    const int bm = blockIdx.x * 128;
    const int bn = blockIdx.y * 128;

    const __nv_bfloat16* __restrict__ Ahi = (MODE == 0) ? gXhi : gOhi;
    const __nv_bfloat16* __restrict__ Alo = (MODE == 0) ? gXlo : gOlo;
    const __nv_bfloat16* __restrict__ Bhi = (MODE == 0) ? gW1hi : gW2hi;
    const __nv_bfloat16* __restrict__ Blo = (MODE == 0) ? gW1lo : gW2lo;

    float acc[2][8][4] = {};

    for (int k0 = 0; k0 < EMB; k0 += 64) {
        // ---- fill smem tiles (hi/lo for A and B), 128x64 bf16 each ----
#pragma unroll
        for (int u = 0; u < 4; ++u) {
            int i = tid + u * 256;            // 0..1023
            int r = i >> 3, cb = (i & 7) * 8; // row, col-block of 8 bf16
            size_t goA = (size_t)(bm + r) * EMB + k0 + cb;
            size_t goB = (size_t)(bn + r) * EMB + k0 + cb;
            *reinterpret_cast<uint4*>(&sAh[r * SMEM_PITCH + cb]) =
                *reinterpret_cast<const uint4*>(Ahi + goA);
            *reinterpret_cast<uint4*>(&sAl[r * SMEM_PITCH + cb]) =
                *reinterpret_cast<const uint4*>(Alo + goA);
            *reinterpret_cast<uint4*>(&sBh[r * SMEM_PITCH + cb]) =
                *reinterpret_cast<const uint4*>(Bhi + goB);
            *reinterpret_cast<uint4*>(&sBl[r * SMEM_PITCH + cb]) =
                *reinterpret_cast<const uint4*>(Blo + goB);
        }
        __syncthreads();

        // ---- compute: 4 k16 substeps ----
#pragma unroll
        for (int ks = 0; ks < 4; ++ks) {
            const int kc = ks * 16 + tig * 2;
            uint32_t ah[2][4], al[2][4];
#pragma unroll
            for (int mt = 0; mt < 2; ++mt) {
                const int r0 = wm * 32 + mt * 16 + g;
                ah[mt][0] = *reinterpret_cast<const uint32_t*>(&sAh[r0 * SMEM_PITCH + kc]);
                ah[mt][1] = *reinterpret_cast<const uint32_t*>(&sAh[(r0 + 8) * SMEM_PITCH + kc]);
                ah[mt][2] = *reinterpret_cast<const uint32_t*>(&sAh[r0 * SMEM_PITCH + kc + 8]);
                ah[mt][3] = *reinterpret_cast<const uint32_t*>(&sAh[(r0 + 8) * SMEM_PITCH + kc + 8]);
                al[mt][0] = *reinterpret_cast<const uint32_t*>(&sAl[r0 * SMEM_PITCH + kc]);
                al[mt][1] = *reinterpret_cast<const uint32_t*>(&sAl[(r0 + 8) * SMEM_PITCH + kc]);
                al[mt][2] = *reinterpret_cast<const uint32_t*>(&sAl[r0 * SMEM_PITCH + kc + 8]);
                al[mt][3] = *reinterpret_cast<const uint32_t*>(&sAl[(r0 + 8) * SMEM_PITCH + kc + 8]);
            }
#pragma unroll
            for (int nt = 0; nt < 8; ++nt) {
                const int n0 = wn * 64 + nt * 8 + g;
                uint32_t bh[2], bl[2];
                bh[0] = *reinterpret_cast<const uint32_t*>(&sBh[n0 * SMEM_PITCH + kc]);
                bh[1] = *reinterpret_cast<const uint32_t*>(&sBh[n0 * SMEM_PITCH + kc + 8]);
                bl[0] = *reinterpret_cast<const uint32_t*>(&sBl[n0 * SMEM_PITCH + kc]);
                bl[1] = *reinterpret_cast<const uint32_t*>(&sBl[n0 * SMEM_PITCH + kc + 8]);
#pragma unroll
                for (int mt = 0; mt < 2; ++mt) {
                    mma16816(acc[mt][nt], ah[mt], bh);
                    mma16816(acc[mt][nt], ah[mt], bl);
                    mma16816(acc[mt][nt], al[mt], bh);
                }
            }
        }
        __syncthreads();
    }

    // ---- epilogue ----
    if (MODE == 0) {
#pragma unroll
        for (int mt = 0; mt < 2; ++mt) {
#pragma unroll
            for (int nt = 0; nt < 8; ++nt) {
#pragma unroll
                for (int e = 0; e < 4; ++e) {
                    const int m = bm + wm * 32 + mt * 16 + g + (e >> 1) * 8;
                    const int f = bn + wn * 64 + nt * 8 + tig * 2 + (e & 1);
                    float v = acc[mt][nt][e] + __ldg(&bias[f]);
                    const int ii = f / 3;
                    const int s  = f - ii * 3;
                    const int head = ii >> 6;
                    const int dd   = ii & 63;
                    const int l = m >> 2;
                    const int n = m & 3;
                    const size_t off = (((size_t)(n * H + head) * L_SEQ + l) << 6) + dd;
                    if (s == 0)      g_Q[off] = v * QSCALE;
                    else if (s == 1) g_K[off] = v;
                    else             g_V[off] = v;
                }
            }
        }
    } else {
#pragma unroll
        for (int mt = 0; mt < 2; ++mt) {
#pragma unroll
            for (int nt = 0; nt < 8; ++nt) {
                const int f = bn + wn * 64 + nt * 8 + tig * 2;
                const float b0 = __ldg(&bias[f]);
                const float b1 = __ldg(&bias[f + 1]);
                const int m0 = bm + wm * 32 + mt * 16 + g;
                float2 v0 = make_float2(acc[mt][nt][0] + b0, acc[mt][nt][1] + b1);
                float2 v1 = make_float2(acc[mt][nt][2] + b0, acc[mt][nt][3] + b1);
                *reinterpret_cast<float2*>(outp + (size_t)m0 * EMB + f) = v0;
                *reinterpret_cast<float2*>(outp + (size_t)(m0 + 8) * EMB + f) = v1;
            }
        }
    }
}

// ---------------------------------------------------------------------------
// Flash attention (SIMT mainloop); epilogue emits bf16 hi/lo for out-proj
// ---------------------------------------------------------------------------
__device__ __forceinline__ float redmax16(float v) {
    v = fmaxf(v, __shfl_xor_sync(0xffffffffu, v, 1));
    v = fmaxf(v, __shfl_xor_sync(0xffffffffu, v, 2));
    v = fmaxf(v, __shfl_xor_sync(0xffffffffu, v, 4));
    v = fmaxf(v, __shfl_xor_sync(0xffffffffu, v, 8));
    return v;
}
__device__ __forceinline__ float redsum16(float v) {
    v += __shfl_xor_sync(0xffffffffu, v, 1);
    v += __shfl_xor_sync(0xffffffffu, v, 2);
    v += __shfl_xor_sync(0xffffffffu, v, 4);
    v += __shfl_xor_sync(0xffffffffu, v, 8);
    return v;
}

#define ATTN_SMEM (4 * 64 * 64 * 4)  // 65536 bytes

__global__ __launch_bounds__(256) void attn_kernel()
{
    extern __shared__ float smemf[];
    float* Qs = smemf;
    float* Ks = smemf + 4096;
    float* Vs = smemf + 8192;
    float* Pt = smemf + 12288;

    const int b  = blockIdx.y;
    const int qt = blockIdx.x;

    const int tx = threadIdx.x & 15;
    const int ty = threadIdx.x >> 4;
    const int lr = threadIdx.x >> 2;
    const int c0 = (threadIdx.x & 3) * 4;

    const float* Qg = g_Q + ((size_t)b * L_SEQ + qt * 64) * DHEAD;

#pragma unroll
    for (int it = 0; it < 4; ++it) {
        const int c = c0 + it * 16;
        float4 q = *reinterpret_cast<const float4*>(&Qg[lr * DHEAD + c]);
        Qs[(c + 0) * 64 + lr] = q.x; Qs[(c + 1) * 64 + lr] = q.y;
        Qs[(c + 2) * 64 + lr] = q.z; Qs[(c + 3) * 64 + lr] = q.w;
    }

    float m_run[4] = {-INFINITY, -INFINITY, -INFINITY, -INFINITY};
    float l_run[4] = {0.f, 0.f, 0.f, 0.f};
    float acc[4][4] = {};

    for (int kt = 0; kt < L_SEQ / 64; ++kt) {
        const float* Kg = g_K + ((size_t)b * L_SEQ + kt * 64) * DHEAD;
        const float* Vg = g_V + ((size_t)b * L_SEQ + kt * 64) * DHEAD;
#pragma unroll
        for (int it = 0; it < 4; ++it) {
            const int c = c0 + it * 16;
            float4 k4 = *reinterpret_cast<const float4*>(&Kg[lr * DHEAD + c]);
            Ks[(c + 0) * 64 + lr] = k4.x; Ks[(c + 1) * 64 + lr] = k4.y;
            Ks[(c + 2) * 64 + lr] = k4.z; Ks[(c + 3) * 64 + lr] = k4.w;
            float4 v4 = *reinterpret_cast<const float4*>(&Vg[lr * DHEAD + c]);
            *reinterpret_cast<float4*>(&Vs[lr * 64 + c]) = v4;
        }
        __syncthreads();

        float s[4][4] = {};
#pragma unroll
        for (int dd = 0; dd < 64; ++dd) {
            float4 qv4 = *reinterpret_cast<const float4*>(&Qs[dd * 64 + ty * 4]);
            float4 kv4 = *reinterpret_cast<const float4*>(&Ks[dd * 64 + tx * 4]);
            float qv[4] = {qv4.x, qv4.y, qv4.z, qv4.w};
            float kv[4] = {kv4.x, kv4.y, kv4.z, kv4.w};
#pragma unroll
            for (int i = 0; i < 4; ++i)
#pragma unroll
                for (int j = 0; j < 4; ++j)
                    s[i][j] = fmaf(qv[i], kv[j], s[i][j]);
        }

#pragma unroll
        for (int i = 0; i < 4; ++i) {
            float mx = fmaxf(fmaxf(s[i][0], s[i][1]), fmaxf(s[i][2], s[i][3]));
            mx = redmax16(mx);
            const float newm = fmaxf(m_run[i], mx);
            const float corr = __expf(m_run[i] - newm);
            m_run[i] = newm;
            float rs = 0.f;
#pragma unroll
            for (int j = 0; j < 4; ++j) {
                const float p = __expf(s[i][j] - newm);
                s[i][j] = p;
                rs += p;
            }
            rs = redsum16(rs);
            l_run[i] = l_run[i] * corr + rs;
#pragma unroll
            for (int j = 0; j < 4; ++j) acc[i][j] *= corr;
        }

#pragma unroll
        for (int i = 0; i < 4; ++i)
#pragma unroll
            for (int j = 0; j < 4; ++j)
                Pt[(tx * 4 + j) * 64 + (ty * 4 + i)] = s[i][j];
        __syncthreads();

#pragma unroll
        for (int j = 0; j < 64; ++j) {
            float4 pv4 = *reinterpret_cast<const float4*>(&Pt[j * 64 + ty * 4]);
            float4 vv4 = *reinterpret_cast<const float4*>(&Vs[j * 64 + tx * 4]);
            float pv[4] = {pv4.x, pv4.y, pv4.z, pv4.w};
            float vv[4] = {vv4.x, vv4.y, vv4.z, vv4.w};
#pragma unroll
            for (int i = 0; i < 4; ++i)
#pragma unroll
                for (int jj = 0; jj < 4; ++jj)
                    acc[i][jj] = fmaf(pv[i], vv[jj], acc[i][jj]);
        }
        __syncthreads();
    }

    // Epilogue: normalize and write bf16 hi/lo split of O
    const int n    = b >> 4;
    const int head = b & 15;
#pragma unroll
    for (int i = 0; i < 4; ++i) {
        const float inv = 1.0f / l_run[i];
        const int lg = qt * 64 + ty * 4 + i;
        const size_t base = ((size_t)lg * NB + n) * INNER + head * DHEAD + tx * 4;
        unsigned short hs[4], ls[4];
#pragma unroll
        for (int k = 0; k < 4; ++k) {
            float v = acc[i][k] * inv;
            __nv_bfloat16 h = __float2bfloat16(v);
            __nv_bfloat16 l = __float2bfloat16(v - __bfloat162float(h));
            hs[k] = __bfloat16_as_ushort(h);
            ls[k] = __bfloat16_as_ushort(l);
        }
        uint2 uh, ul;
        uh.x = (uint32_t)hs[0] | ((uint32_t)hs[1] << 16);
        uh.y = (uint32_t)hs[2] | ((uint32_t)hs[3] << 16);
        ul.x = (uint32_t)ls[0] | ((uint32_t)ls[1] << 16);
        ul.y = (uint32_t)ls[2] | ((uint32_t)ls[3] << 16);
        *reinterpret_cast<uint2*>(&gOhi[base]) = uh;
        *reinterpret_cast<uint2*>(&gOlo[base]) = ul;
    }
}

// ---------------------------------------------------------------------------
// Launcher
// ---------------------------------------------------------------------------
extern "C" void kernel_launch(void* const* d_in, const int* in_sizes, int n_in,
                              void* d_out, int out_size)
{
    const float* query    = (const float*)d_in[0];
    const float* qkv_proj = (const float*)d_in[1];
    const float* qkv_bias = (const float*)d_in[2];
    const float* out_proj = (const float*)d_in[3];
    const float* out_bias = (const float*)d_in[4];
    float* out = (float*)d_out;

    static bool init_done = false;
    if (!init_done) {
        cudaFuncSetAttribute(attn_kernel,
                             cudaFuncAttributeMaxDynamicSharedMemorySize, ATTN_SMEM);
        cudaFuncSetAttribute(mma_gemm<0>,
                             cudaFuncAttributeMaxDynamicSharedMemorySize, GEMM_SMEM);
        cudaFuncSetAttribute(mma_gemm<1>,
                             cudaFuncAttributeMaxDynamicSharedMemorySize, GEMM_SMEM);
        init_done = true;
    }

    convert_kernel<0><<<1184, 256>>>(query,    (M_ROWS * EMB) / 4);
    convert_kernel<1><<<1184, 256>>>(qkv_proj, (3 * INNER * EMB) / 4);
    convert_kernel<2><<<592, 256>>>(out_proj,  (EMB * INNER) / 4);

    dim3 g1(M_ROWS / 128, (3 * INNER) / 128);
    mma_gemm<0><<<g1, 256, GEMM_SMEM>>>(qkv_bias, nullptr);

    dim3 g2(L_SEQ / 64, BATCH);
    attn_kernel<<<g2, 256, ATTN_SMEM>>>();

    dim3 g3(M_ROWS / 128, EMB / 128);
    mma_gemm<1><<<g3, 256, GEMM_SMEM>>>(out_bias, out);
}

// round 4
// speedup vs baseline: 2.5889x; 1.7253x over previous
#include <cuda_runtime.h>
#include <cuda_bf16.h>
#include <math.h>
#include <stdint.h>

// ---------------------------------------------------------------------------
// Problem constants
// ---------------------------------------------------------------------------
#define L_SEQ 2048
#define NB    4
#define EMB   1024
#define INNER 1024
#define H     16
#define DHEAD 64
#define BATCH (NB * H)          // 64
#define M_ROWS (L_SEQ * NB)     // 8192
#define QSCALE 0.125f

// ---------------------------------------------------------------------------
// Device-global scratch (no allocation allowed)
// ---------------------------------------------------------------------------
__device__ __nv_bfloat16 gXhi[(size_t)M_ROWS * EMB];
__device__ __nv_bfloat16 gXlo[(size_t)M_ROWS * EMB];
__device__ __nv_bfloat16 gW1hi[(size_t)3 * INNER * EMB];
__device__ __nv_bfloat16 gW1lo[(size_t)3 * INNER * EMB];
__device__ __nv_bfloat16 gW2hi[(size_t)EMB * INNER];
__device__ __nv_bfloat16 gW2lo[(size_t)EMB * INNER];
__device__ __nv_bfloat16 gOhi[(size_t)M_ROWS * INNER];
__device__ __nv_bfloat16 gOlo[(size_t)M_ROWS * INNER];

// Attention operands, bf16 hi/lo. Q,K: [b][l][dd]; Vt: [b][dd][l]
__device__ __nv_bfloat16 gQhi[(size_t)BATCH * L_SEQ * DHEAD];
__device__ __nv_bfloat16 gQlo[(size_t)BATCH * L_SEQ * DHEAD];
__device__ __nv_bfloat16 gKhi[(size_t)BATCH * L_SEQ * DHEAD];
__device__ __nv_bfloat16 gKlo[(size_t)BATCH * L_SEQ * DHEAD];
__device__ __nv_bfloat16 gVthi[(size_t)BATCH * DHEAD * L_SEQ];
__device__ __nv_bfloat16 gVtlo[(size_t)BATCH * DHEAD * L_SEQ];

// ---------------------------------------------------------------------------
// warp mma helper: m16n8k16 row.col f32 += bf16 * bf16
// ---------------------------------------------------------------------------
__device__ __forceinline__ void mma16816(float* d, const uint32_t* a, const uint32_t* b)
{
    asm volatile(
        "mma.sync.aligned.m16n8k16.row.col.f32.bf16.bf16.f32 "
        "{%0,%1,%2,%3}, {%4,%5,%6,%7}, {%8,%9}, {%0,%1,%2,%3};"
        : "+f"(d[0]), "+f"(d[1]), "+f"(d[2]), "+f"(d[3])
        : "r"(a[0]), "r"(a[1]), "r"(a[2]), "r"(a[3]), "r"(b[0]), "r"(b[1]));
}

// pack two floats to bf16x2 (lo in low half)
__device__ __forceinline__ uint32_t pack_bf16x2(float lo, float hi)
{
    uint32_t r;
    asm("cvt.rn.bf16x2.f32 %0, %1, %2;" : "=r"(r) : "f"(hi), "f"(lo));
    return r;
}
__device__ __forceinline__ float bf16_hi_part(float v)
{
    // fp32 value of round-to-nearest bf16 of v
    __nv_bfloat16 h = __float2bfloat16(v);
    return __bfloat162float(h);
}

// ---------------------------------------------------------------------------
// Pre-pass: fp32 -> bf16 hi/lo split
// ---------------------------------------------------------------------------
template<int WHICH>
__global__ __launch_bounds__(256) void convert_kernel(const float* __restrict__ src, int n4)
{
    __nv_bfloat16* hi = (WHICH == 0) ? gXhi : (WHICH == 1) ? gW1hi : gW2hi;
    __nv_bfloat16* lo = (WHICH == 0) ? gXlo : (WHICH == 1) ? gW1lo : gW2lo;
    for (int i = blockIdx.x * blockDim.x + threadIdx.x; i < n4;
         i += gridDim.x * blockDim.x) {
        float4 v = reinterpret_cast<const float4*>(src)[i];
        float f[4] = {v.x, v.y, v.z, v.w};
        unsigned short hs[4], ls[4];
#pragma unroll
        for (int k = 0; k < 4; ++k) {
            __nv_bfloat16 h = __float2bfloat16(f[k]);
            __nv_bfloat16 l = __float2bfloat16(f[k] - __bfloat162float(h));
            hs[k] = __bfloat16_as_ushort(h);
            ls[k] = __bfloat16_as_ushort(l);
        }
        uint2 uh, ul;
        uh.x = (uint32_t)hs[0] | ((uint32_t)hs[1] << 16);
        uh.y = (uint32_t)hs[2] | ((uint32_t)hs[3] << 16);
        ul.x = (uint32_t)ls[0] | ((uint32_t)ls[1] << 16);
        ul.y = (uint32_t)ls[2] | ((uint32_t)ls[3] << 16);
        reinterpret_cast<uint2*>(hi)[i] = uh;
        reinterpret_cast<uint2*>(lo)[i] = ul;
    }
}

// ---------------------------------------------------------------------------
// Split-bf16 warp-MMA GEMM.  C[m][f] = sum_k A[m][k]*B[f][k] + bias[f]
// MODE 0: epilogue de-interleaves into bf16 hi/lo Q (scaled) / K / Vt.
// MODE 1: epilogue writes fp32 d_out.
// Block tile 128x128x64, 256 threads = 8 warps (4m x 2n), warp tile 32x64.
// ---------------------------------------------------------------------------
#define SMEM_PITCH 72
#define SMEM_ARR (128 * SMEM_PITCH)
#define GEMM_SMEM (4 * SMEM_ARR * 2)   // 73728 bytes

template<int MODE>
__global__ __launch_bounds__(256) void mma_gemm(const float* __restrict__ bias,
                                                float* __restrict__ outp)
{
    extern __shared__ __nv_bfloat16 sm[];
    __nv_bfloat16* sAh = sm;
    __nv_bfloat16* sAl = sm + SMEM_ARR;
    __nv_bfloat16* sBh = sm + 2 * SMEM_ARR;
    __nv_bfloat16* sBl = sm + 3 * SMEM_ARR;

    const int tid = threadIdx.x;
    const int wid = tid >> 5;
    const int lane = tid & 31;
    const int g   = lane >> 2;
    const int tig = lane & 3;
    const int wm = wid >> 1;
    const int wn = wid & 1;
    const int bm = blockIdx.x * 128;
    const int bn = blockIdx.y * 128;

    const __nv_bfloat16* __restrict__ Ahi = (MODE == 0) ? gXhi : gOhi;
    const __nv_bfloat16* __restrict__ Alo = (MODE == 0) ? gXlo : gOlo;
    const __nv_bfloat16* __restrict__ Bhi = (MODE == 0) ? gW1hi : gW2hi;
    const __nv_bfloat16* __restrict__ Blo = (MODE == 0) ? gW1lo : gW2lo;

    float acc[2][8][4] = {};

    for (int k0 = 0; k0 < EMB; k0 += 64) {
#pragma unroll
        for (int u = 0; u < 4; ++u) {
            int i = tid + u * 256;
            int r = i >> 3, cb = (i & 7) * 8;
            size_t goA = (size_t)(bm + r) * EMB + k0 + cb;
            size_t goB = (size_t)(bn + r) * EMB + k0 + cb;
            *reinterpret_cast<uint4*>(&sAh[r * SMEM_PITCH + cb]) =
                *reinterpret_cast<const uint4*>(Ahi + goA);
            *reinterpret_cast<uint4*>(&sAl[r * SMEM_PITCH + cb]) =
                *reinterpret_cast<const uint4*>(Alo + goA);
            *reinterpret_cast<uint4*>(&sBh[r * SMEM_PITCH + cb]) =
                *reinterpret_cast<const uint4*>(Bhi + goB);
            *reinterpret_cast<uint4*>(&sBl[r * SMEM_PITCH + cb]) =
                *reinterpret_cast<const uint4*>(Blo + goB);
        }
        __syncthreads();

#pragma unroll
        for (int ks = 0; ks < 4; ++ks) {
            const int kc = ks * 16 + tig * 2;
            uint32_t ah[2][4], al[2][4];
#pragma unroll
            for (int mt = 0; mt < 2; ++mt) {
                const int r0 = wm * 32 + mt * 16 + g;
                ah[mt][0] = *reinterpret_cast<const uint32_t*>(&sAh[r0 * SMEM_PITCH + kc]);
                ah[mt][1] = *reinterpret_cast<const uint32_t*>(&sAh[(r0 + 8) * SMEM_PITCH + kc]);
                ah[mt][2] = *reinterpret_cast<const uint32_t*>(&sAh[r0 * SMEM_PITCH + kc + 8]);
                ah[mt][3] = *reinterpret_cast<const uint32_t*>(&sAh[(r0 + 8) * SMEM_PITCH + kc + 8]);
                al[mt][0] = *reinterpret_cast<const uint32_t*>(&sAl[r0 * SMEM_PITCH + kc]);
                al[mt][1] = *reinterpret_cast<const uint32_t*>(&sAl[(r0 + 8) * SMEM_PITCH + kc]);
                al[mt][2] = *reinterpret_cast<const uint32_t*>(&sAl[r0 * SMEM_PITCH + kc + 8]);
                al[mt][3] = *reinterpret_cast<const uint32_t*>(&sAl[(r0 + 8) * SMEM_PITCH + kc + 8]);
            }
#pragma unroll
            for (int nt = 0; nt < 8; ++nt) {
                const int n0 = wn * 64 + nt * 8 + g;
                uint32_t bh[2], bl[2];
                bh[0] = *reinterpret_cast<const uint32_t*>(&sBh[n0 * SMEM_PITCH + kc]);
                bh[1] = *reinterpret_cast<const uint32_t*>(&sBh[n0 * SMEM_PITCH + kc + 8]);
                bl[0] = *reinterpret_cast<const uint32_t*>(&sBl[n0 * SMEM_PITCH + kc]);
                bl[1] = *reinterpret_cast<const uint32_t*>(&sBl[n0 * SMEM_PITCH + kc + 8]);
#pragma unroll
                for (int mt = 0; mt < 2; ++mt) {
                    mma16816(acc[mt][nt], ah[mt], bh);
                    mma16816(acc[mt][nt], ah[mt], bl);
                    mma16816(acc[mt][nt], al[mt], bh);
                }
            }
        }
        __syncthreads();
    }

    // ---- epilogue ----
    if (MODE == 0) {
#pragma unroll
        for (int mt = 0; mt < 2; ++mt) {
#pragma unroll
            for (int nt = 0; nt < 8; ++nt) {
#pragma unroll
                for (int e = 0; e < 4; ++e) {
                    const int m = bm + wm * 32 + mt * 16 + g + (e >> 1) * 8;
                    const int f = bn + wn * 64 + nt * 8 + tig * 2 + (e & 1);
                    float v = acc[mt][nt][e] + __ldg(&bias[f]);
                    const int ii = f / 3;
                    const int s  = f - ii * 3;
                    const int head = ii >> 6;
                    const int dd   = ii & 63;
                    const int l = m >> 2;
                    const int n = m & 3;
                    const int b = n * H + head;
                    if (s == 0) v *= QSCALE;
                    __nv_bfloat16 h = __float2bfloat16(v);
                    __nv_bfloat16 lo = __float2bfloat16(v - __bfloat162float(h));
                    if (s == 2) {
                        const size_t off = ((size_t)b * DHEAD + dd) * L_SEQ + l;
                        gVthi[off] = h; gVtlo[off] = lo;
                    } else {
                        const size_t off = (((size_t)b * L_SEQ + l) << 6) + dd;
                        if (s == 0) { gQhi[off] = h; gQlo[off] = lo; }
                        else        { gKhi[off] = h; gKlo[off] = lo; }
                    }
                }
            }
        }
    } else {
#pragma unroll
        for (int mt = 0; mt < 2; ++mt) {
#pragma unroll
            for (int nt = 0; nt < 8; ++nt) {
                const int f = bn + wn * 64 + nt * 8 + tig * 2;
                const float b0 = __ldg(&bias[f]);
                const float b1 = __ldg(&bias[f + 1]);
                const int m0 = bm + wm * 32 + mt * 16 + g;
                float2 v0 = make_float2(acc[mt][nt][0] + b0, acc[mt][nt][1] + b1);
                float2 v1 = make_float2(acc[mt][nt][2] + b0, acc[mt][nt][3] + b1);
                *reinterpret_cast<float2*>(outp + (size_t)m0 * EMB + f) = v0;
                *reinterpret_cast<float2*>(outp + (size_t)(m0 + 8) * EMB + f) = v1;
            }
        }
    }
}

// ---------------------------------------------------------------------------
// Tensor-core flash attention.
// Block: (qt, b). 128 threads = 4 warps; warp owns 16 q-rows.
// S(64x64) = Q@K^T via split-bf16 mma; online softmax in fragment layout;
// O += P@Vt via split mma (Ph*Vh + Pl*Vh + Ph*Vl).
// ---------------------------------------------------------------------------
#define AP 72
#define AARR (64 * AP)
#define ATTN_SMEM (6 * AARR * 2)   // 55296 bytes

__global__ __launch_bounds__(128) void attn_mma_kernel()
{
    extern __shared__ __nv_bfloat16 asm_[];
    __nv_bfloat16* sQh = asm_;
    __nv_bfloat16* sQl = asm_ + AARR;
    __nv_bfloat16* sKh = asm_ + 2 * AARR;
    __nv_bfloat16* sKl = asm_ + 3 * AARR;
    __nv_bfloat16* sVh = asm_ + 4 * AARR;   // Vt layout: [dd][l]
    __nv_bfloat16* sVl = asm_ + 5 * AARR;

    const int qt = blockIdx.x;   // 0..31
    const int b  = blockIdx.y;   // 0..63
    const int tid = threadIdx.x;
    const int wid = tid >> 5;    // 0..3
    const int lane = tid & 31;
    const int g   = lane >> 2;
    const int tig = lane & 3;

    // ---- load Q tile (64 rows) to smem, coalesced ----
    {
        const __nv_bfloat16* Qh = gQhi + (((size_t)b * L_SEQ + qt * 64) << 6);
        const __nv_bfloat16* Ql = gQlo + (((size_t)b * L_SEQ + qt * 64) << 6);
#pragma unroll
        for (int u = 0; u < 4; ++u) {
            int i = tid + u * 128;
            int r = i >> 3, cb = (i & 7) * 8;
            *reinterpret_cast<uint4*>(&sQh[r * AP + cb]) =
                *reinterpret_cast<const uint4*>(Qh + r * 64 + cb);
            *reinterpret_cast<uint4*>(&sQl[r * AP + cb]) =
                *reinterpret_cast<const uint4*>(Ql + r * 64 + cb);
        }
    }
    __syncthreads();

    // ---- Q fragments in registers (persist whole kernel) ----
    uint32_t qh[4][4], ql[4][4];
    {
        const int r0 = wid * 16 + g;
#pragma unroll
        for (int ks = 0; ks < 4; ++ks) {
            const int kc = ks * 16 + tig * 2;
            qh[ks][0] = *reinterpret_cast<const uint32_t*>(&sQh[r0 * AP + kc]);
            qh[ks][1] = *reinterpret_cast<const uint32_t*>(&sQh[(r0 + 8) * AP + kc]);
            qh[ks][2] = *reinterpret_cast<const uint32_t*>(&sQh[r0 * AP + kc + 8]);
            qh[ks][3] = *reinterpret_cast<const uint32_t*>(&sQh[(r0 + 8) * AP + kc + 8]);
            ql[ks][0] = *reinterpret_cast<const uint32_t*>(&sQl[r0 * AP + kc]);
            ql[ks][1] = *reinterpret_cast<const uint32_t*>(&sQl[(r0 + 8) * AP + kc]);
            ql[ks][2] = *reinterpret_cast<const uint32_t*>(&sQl[r0 * AP + kc + 8]);
            ql[ks][3] = *reinterpret_cast<const uint32_t*>(&sQl[(r0 + 8) * AP + kc + 8]);
        }
    }

    float m0 = -INFINITY, m1 = -INFINITY, l0 = 0.f, l1 = 0.f;
    float o[8][4] = {};

    const __nv_bfloat16* Khb = gKhi + (((size_t)b * L_SEQ) << 6);
    const __nv_bfloat16* Klb = gKlo + (((size_t)b * L_SEQ) << 6);
    const __nv_bfloat16* Vhb = gVthi + (size_t)b * DHEAD * L_SEQ;
    const __nv_bfloat16* Vlb = gVtlo + (size_t)b * DHEAD * L_SEQ;

    for (int kt = 0; kt < L_SEQ / 64; ++kt) {
        // ---- stage K (rows=key) and Vt (rows=dd) tiles ----
#pragma unroll
        for (int u = 0; u < 4; ++u) {
            int i = tid + u * 128;
            int r = i >> 3, cb = (i & 7) * 8;
            *reinterpret_cast<uint4*>(&sKh[r * AP + cb]) =
                *reinterpret_cast<const uint4*>(Khb + ((size_t)(kt * 64 + r) << 6) + cb);
            *reinterpret_cast<uint4*>(&sKl[r * AP + cb]) =
                *reinterpret_cast<const uint4*>(Klb + ((size_t)(kt * 64 + r) << 6) + cb);
            *reinterpret_cast<uint4*>(&sVh[r * AP + cb]) =
                *reinterpret_cast<const uint4*>(Vhb + (size_t)r * L_SEQ + kt * 64 + cb);
            *reinterpret_cast<uint4*>(&sVl[r * AP + cb]) =
                *reinterpret_cast<const uint4*>(Vlb + (size_t)r * L_SEQ + kt * 64 + cb);
        }
        __syncthreads();

        // ---- S = Q @ K^T (split bf16) ----
        float s[8][4] = {};
#pragma unroll
        for (int ks = 0; ks < 4; ++ks) {
            const int kc = ks * 16 + tig * 2;
#pragma unroll
            for (int nt = 0; nt < 8; ++nt) {
                const int n0 = nt * 8 + g;
                uint32_t bh[2], bl[2];
                bh[0] = *reinterpret_cast<const uint32_t*>(&sKh[n0 * AP + kc]);
                bh[1] = *reinterpret_cast<const uint32_t*>(&sKh[n0 * AP + kc + 8]);
                bl[0] = *reinterpret_cast<const uint32_t*>(&sKl[n0 * AP + kc]);
                bl[1] = *reinterpret_cast<const uint32_t*>(&sKl[n0 * AP + kc + 8]);
                mma16816(s[nt], qh[ks], bh);
                mma16816(s[nt], qh[ks], bl);
                mma16816(s[nt], ql[ks], bh);
            }
        }

        // ---- online softmax (rows g and g+8) ----
        float mx0 = -INFINITY, mx1 = -INFINITY;
#pragma unroll
        for (int nt = 0; nt < 8; ++nt) {
            mx0 = fmaxf(mx0, fmaxf(s[nt][0], s[nt][1]));
            mx1 = fmaxf(mx1, fmaxf(s[nt][2], s[nt][3]));
        }
        mx0 = fmaxf(mx0, __shfl_xor_sync(0xffffffffu, mx0, 1));
        mx0 = fmaxf(mx0, __shfl_xor_sync(0xffffffffu, mx0, 2));
        mx1 = fmaxf(mx1, __shfl_xor_sync(0xffffffffu, mx1, 1));
        mx1 = fmaxf(mx1, __shfl_xor_sync(0xffffffffu, mx1, 2));

        const float nm0 = fmaxf(m0, mx0);
        const float nm1 = fmaxf(m1, mx1);
        const float c0 = __expf(m0 - nm0);
        const float c1 = __expf(m1 - nm1);
        m0 = nm0; m1 = nm1;

        float rs0 = 0.f, rs1 = 0.f;
        uint32_t ph[4][4], pl[4][4];
#pragma unroll
        for (int nt = 0; nt < 8; ++nt) {
            float p0 = __expf(s[nt][0] - nm0);
            float p1 = __expf(s[nt][1] - nm0);
            float p2 = __expf(s[nt][2] - nm1);
            float p3 = __expf(s[nt][3] - nm1);
            rs0 += p0 + p1;
            rs1 += p2 + p3;
            float h0 = bf16_hi_part(p0), h1 = bf16_hi_part(p1);
            float h2 = bf16_hi_part(p2), h3 = bf16_hi_part(p3);
            const int ks2 = nt >> 1;
            const int half = (nt & 1) * 2;
            ph[ks2][half + 0] = pack_bf16x2(h0, h1);
            ph[ks2][half + 1] = pack_bf16x2(h2, h3);
            pl[ks2][half + 0] = pack_bf16x2(p0 - h0, p1 - h1);
            pl[ks2][half + 1] = pack_bf16x2(p2 - h2, p3 - h3);
        }
        rs0 += __shfl_xor_sync(0xffffffffu, rs0, 1);
        rs0 += __shfl_xor_sync(0xffffffffu, rs0, 2);
        rs1 += __shfl_xor_sync(0xffffffffu, rs1, 1);
        rs1 += __shfl_xor_sync(0xffffffffu, rs1, 2);
        l0 = l0 * c0 + rs0;
        l1 = l1 * c1 + rs1;

#pragma unroll
        for (int nt = 0; nt < 8; ++nt) {
            o[nt][0] *= c0; o[nt][1] *= c0;
            o[nt][2] *= c1; o[nt][3] *= c1;
        }

        // ---- O += P @ Vt (split bf16) ----
#pragma unroll
        for (int ks2 = 0; ks2 < 4; ++ks2) {
            const int kc = ks2 * 16 + tig * 2;
#pragma unroll
            for (int nt = 0; nt < 8; ++nt) {
                const int n0 = nt * 8 + g;
                uint32_t bh[2], bl[2];
                bh[0] = *reinterpret_cast<const uint32_t*>(&sVh[n0 * AP + kc]);
                bh[1] = *reinterpret_cast<const uint32_t*>(&sVh[n0 * AP + kc + 8]);
                bl[0] = *reinterpret_cast<const uint32_t*>(&sVl[n0 * AP + kc]);
                bl[1] = *reinterpret_cast<const uint32_t*>(&sVl[n0 * AP + kc + 8]);
                mma16816(o[nt], ph[ks2], bh);
                mma16816(o[nt], pl[ks2], bh);
                mma16816(o[nt], ph[ks2], bl);
            }
        }
        __syncthreads();
    }

    // ---- epilogue: normalize, hi/lo split, write gO ----
    const float inv0 = 1.0f / l0;
    const float inv1 = 1.0f / l1;
    const int n    = b >> 4;
    const int head = b & 15;
    const int lg0 = qt * 64 + wid * 16 + g;
    const int lg1 = lg0 + 8;
#pragma unroll
    for (int nt = 0; nt < 8; ++nt) {
        const int dd = nt * 8 + tig * 2;
        const size_t base0 = ((size_t)lg0 * NB + n) * INNER + head * DHEAD + dd;
        const size_t base1 = ((size_t)lg1 * NB + n) * INNER + head * DHEAD + dd;
        float v0 = o[nt][0] * inv0, v1 = o[nt][1] * inv0;
        float v2 = o[nt][2] * inv1, v3 = o[nt][3] * inv1;
        float h0 = bf16_hi_part(v0), h1 = bf16_hi_part(v1);
        float h2 = bf16_hi_part(v2), h3 = bf16_hi_part(v3);
        *reinterpret_cast<uint32_t*>(&gOhi[base0]) = pack_bf16x2(h0, h1);
        *reinterpret_cast<uint32_t*>(&gOlo[base0]) = pack_bf16x2(v0 - h0, v1 - h1);
        *reinterpret_cast<uint32_t*>(&gOhi[base1]) = pack_bf16x2(h2, h3);
        *reinterpret_cast<uint32_t*>(&gOlo[base1]) = pack_bf16x2(v2 - h2, v3 - h3);
    }
}

// ---------------------------------------------------------------------------
// Launcher
// ---------------------------------------------------------------------------
extern "C" void kernel_launch(void* const* d_in, const int* in_sizes, int n_in,
                              void* d_out, int out_size)
{
    const float* query    = (const float*)d_in[0];
    const float* qkv_proj = (const float*)d_in[1];
    const float* qkv_bias = (const float*)d_in[2];
    const float* out_proj = (const float*)d_in[3];
    const float* out_bias = (const float*)d_in[4];
    float* out = (float*)d_out;

    static bool init_done = false;
    if (!init_done) {
        cudaFuncSetAttribute(attn_mma_kernel,
                             cudaFuncAttributeMaxDynamicSharedMemorySize, ATTN_SMEM);
        cudaFuncSetAttribute(mma_gemm<0>,
                             cudaFuncAttributeMaxDynamicSharedMemorySize, GEMM_SMEM);
        cudaFuncSetAttribute(mma_gemm<1>,
                             cudaFuncAttributeMaxDynamicSharedMemorySize, GEMM_SMEM);
        init_done = true;
    }

    convert_kernel<0><<<1184, 256>>>(query,    (M_ROWS * EMB) / 4);
    convert_kernel<1><<<1184, 256>>>(qkv_proj, (3 * INNER * EMB) / 4);
    convert_kernel<2><<<592, 256>>>(out_proj,  (EMB * INNER) / 4);

    dim3 g1(M_ROWS / 128, (3 * INNER) / 128);
    mma_gemm<0><<<g1, 256, GEMM_SMEM>>>(qkv_bias, nullptr);

    dim3 g2(L_SEQ / 64, BATCH);
    attn_mma_kernel<<<g2, 128, ATTN_SMEM>>>();

    dim3 g3(M_ROWS / 128, EMB / 128);
    mma_gemm<1><<<g3, 256, GEMM_SMEM>>>(out_bias, out);
}

// round 5
// speedup vs baseline: 2.6345x; 1.0176x over previous
#include <cuda_runtime.h>
#include <cuda_bf16.h>
#include <math.h>
#include <stdint.h>

// ---------------------------------------------------------------------------
// Problem constants
// ---------------------------------------------------------------------------
#define L_SEQ 2048
#define NB    4
#define EMB   1024
#define INNER 1024
#define H     16
#define DHEAD 64
#define BATCH (NB * H)          // 64
#define M_ROWS (L_SEQ * NB)     // 8192
#define QSCALE 0.125f

// ---------------------------------------------------------------------------
// Device-global scratch (no allocation allowed)
// ---------------------------------------------------------------------------
__device__ __nv_bfloat16 gXhi[(size_t)M_ROWS * EMB];
__device__ __nv_bfloat16 gXlo[(size_t)M_ROWS * EMB];
__device__ __nv_bfloat16 gW1hi[(size_t)3 * INNER * EMB];
__device__ __nv_bfloat16 gW1lo[(size_t)3 * INNER * EMB];
__device__ __nv_bfloat16 gW2hi[(size_t)EMB * INNER];
__device__ __nv_bfloat16 gW2lo[(size_t)EMB * INNER];
__device__ __nv_bfloat16 gOhi[(size_t)M_ROWS * INNER];
__device__ __nv_bfloat16 gOlo[(size_t)M_ROWS * INNER];

// Attention operands, bf16 hi/lo. Q,K: [b][l][dd]; Vt: [b][dd][l]
__device__ __nv_bfloat16 gQhi[(size_t)BATCH * L_SEQ * DHEAD];
__device__ __nv_bfloat16 gQlo[(size_t)BATCH * L_SEQ * DHEAD];
__device__ __nv_bfloat16 gKhi[(size_t)BATCH * L_SEQ * DHEAD];
__device__ __nv_bfloat16 gKlo[(size_t)BATCH * L_SEQ * DHEAD];
__device__ __nv_bfloat16 gVthi[(size_t)BATCH * DHEAD * L_SEQ];
__device__ __nv_bfloat16 gVtlo[(size_t)BATCH * DHEAD * L_SEQ];

// ---------------------------------------------------------------------------
// helpers
// ---------------------------------------------------------------------------
__device__ __forceinline__ void mma16816(float* d, const uint32_t* a, const uint32_t* b)
{
    asm volatile(
        "mma.sync.aligned.m16n8k16.row.col.f32.bf16.bf16.f32 "
        "{%0,%1,%2,%3}, {%4,%5,%6,%7}, {%8,%9}, {%0,%1,%2,%3};"
        : "+f"(d[0]), "+f"(d[1]), "+f"(d[2]), "+f"(d[3])
        : "r"(a[0]), "r"(a[1]), "r"(a[2]), "r"(a[3]), "r"(b[0]), "r"(b[1]));
}
__device__ __forceinline__ uint32_t pack_bf16x2(float lo, float hi)
{
    uint32_t r;
    asm("cvt.rn.bf16x2.f32 %0, %1, %2;" : "=r"(r) : "f"(hi), "f"(lo));
    return r;
}
__device__ __forceinline__ float bf16_hi_part(float v)
{
    __nv_bfloat16 h = __float2bfloat16(v);
    return __bfloat162float(h);
}
__device__ __forceinline__ uint32_t smem_u32(const void* p)
{
    uint32_t a;
    asm("{ .reg .u64 t; cvta.to.shared.u64 t, %1; cvt.u32.u64 %0, t; }"
        : "=r"(a) : "l"(p));
    return a;
}
__device__ __forceinline__ void cp16(uint32_t s, const void* g)
{
    asm volatile("cp.async.cg.shared.global [%0], [%1], 16;" :: "r"(s), "l"(g));
}

// ---------------------------------------------------------------------------
// Pre-pass: fp32 -> bf16 hi/lo split
// ---------------------------------------------------------------------------
template<int WHICH>
__global__ __launch_bounds__(256) void convert_kernel(const float* __restrict__ src, int n4)
{
    __nv_bfloat16* hi = (WHICH == 0) ? gXhi : (WHICH == 1) ? gW1hi : gW2hi;
    __nv_bfloat16* lo = (WHICH == 0) ? gXlo : (WHICH == 1) ? gW1lo : gW2lo;
    for (int i = blockIdx.x * blockDim.x + threadIdx.x; i < n4;
         i += gridDim.x * blockDim.x) {
        float4 v = reinterpret_cast<const float4*>(src)[i];
        float f[4] = {v.x, v.y, v.z, v.w};
        unsigned short hs[4], ls[4];
#pragma unroll
        for (int k = 0; k < 4; ++k) {
            __nv_bfloat16 h = __float2bfloat16(f[k]);
            __nv_bfloat16 l = __float2bfloat16(f[k] - __bfloat162float(h));
            hs[k] = __bfloat16_as_ushort(h);
            ls[k] = __bfloat16_as_ushort(l);
        }
        uint2 uh, ul;
        uh.x = (uint32_t)hs[0] | ((uint32_t)hs[1] << 16);
        uh.y = (uint32_t)hs[2] | ((uint32_t)hs[3] << 16);
        ul.x = (uint32_t)ls[0] | ((uint32_t)ls[1] << 16);
        ul.y = (uint32_t)ls[2] | ((uint32_t)ls[3] << 16);
        reinterpret_cast<uint2*>(hi)[i] = uh;
        reinterpret_cast<uint2*>(lo)[i] = ul;
    }
}

// ---------------------------------------------------------------------------
// Split-bf16 warp-MMA GEMM with cp.async double buffering.
// C[m][f] = sum_k A[m][k]*B[f][k] + bias[f]
// Block tile 128x128, BK=32 per stage, 2 stages. 256 threads = 8 warps.
// ---------------------------------------------------------------------------
#define GPITCH 40                       // bf16 elems per row (conflict-free)
#define GARR (128 * GPITCH)             // elems per array (5120)
#define GSTAGE (4 * GARR)               // elems per stage (Ah,Al,Bh,Bl)
#define GEMM_SMEM (2 * GSTAGE * 2)      // 81920 bytes

template<int MODE>
__global__ __launch_bounds__(256, 2) void mma_gemm(const float* __restrict__ bias,
                                                   float* __restrict__ outp)
{
    extern __shared__ __nv_bfloat16 sm[];
    const uint32_t sb = smem_u32(sm);

    const int tid = threadIdx.x;
    const int wid = tid >> 5;
    const int lane = tid & 31;
    const int g   = lane >> 2;
    const int tig = lane & 3;
    const int wm = wid >> 1;
    const int wn = wid & 1;
    const int bm = blockIdx.x * 128;
    const int bn = blockIdx.y * 128;

    const __nv_bfloat16* __restrict__ Ahi = (MODE == 0) ? gXhi : gOhi;
    const __nv_bfloat16* __restrict__ Alo = (MODE == 0) ? gXlo : gOlo;
    const __nv_bfloat16* __restrict__ Bhi = (MODE == 0) ? gW1hi : gW2hi;
    const __nv_bfloat16* __restrict__ Blo = (MODE == 0) ? gW1lo : gW2lo;

    // per-thread async-copy coordinates (2 chunks of 16B per array)
    const int q0 = tid * 2;
    const int r_cp[2]  = { q0 >> 2, (q0 + 1) >> 2 };
    const int cc_cp[2] = { (q0 & 3) * 8, ((q0 + 1) & 3) * 8 };

    auto issue = [&](int ch) {
        const int k0 = ch * 32;
        const uint32_t st = sb + (uint32_t)(ch & 1) * (GSTAGE * 2);
#pragma unroll
        for (int u = 0; u < 2; ++u) {
            const int r = r_cp[u], cc = cc_cp[u];
            const uint32_t so = (uint32_t)(r * GPITCH + cc) * 2;
            const size_t goA = (size_t)(bm + r) * EMB + k0 + cc;
            const size_t goB = (size_t)(bn + r) * EMB + k0 + cc;
            cp16(st + so,                Ahi + goA);
            cp16(st + GARR * 2 + so,     Alo + goA);
            cp16(st + 2 * GARR * 2 + so, Bhi + goB);
            cp16(st + 3 * GARR * 2 + so, Blo + goB);
        }
        asm volatile("cp.async.commit_group;");
    };

    float acc[2][8][4] = {};

    issue(0);

    for (int ch = 0; ch < EMB / 32; ++ch) {
        if (ch + 1 < EMB / 32) {
            issue(ch + 1);
            asm volatile("cp.async.wait_group 1;");
        } else {
            asm volatile("cp.async.wait_group 0;");
        }
        __syncthreads();

        const __nv_bfloat16* pS = sm + (ch & 1) * GSTAGE;
        const __nv_bfloat16* sAh = pS;
        const __nv_bfloat16* sAl = pS + GARR;
        const __nv_bfloat16* sBh = pS + 2 * GARR;
        const __nv_bfloat16* sBl = pS + 3 * GARR;

#pragma unroll
        for (int ks = 0; ks < 2; ++ks) {
            const int kc = ks * 16 + tig * 2;
            uint32_t ah[2][4], al[2][4];
#pragma unroll
            for (int mt = 0; mt < 2; ++mt) {
                const int r0 = wm * 32 + mt * 16 + g;
                ah[mt][0] = *reinterpret_cast<const uint32_t*>(&sAh[r0 * GPITCH + kc]);
                ah[mt][1] = *reinterpret_cast<const uint32_t*>(&sAh[(r0 + 8) * GPITCH + kc]);
                ah[mt][2] = *reinterpret_cast<const uint32_t*>(&sAh[r0 * GPITCH + kc + 8]);
                ah[mt][3] = *reinterpret_cast<const uint32_t*>(&sAh[(r0 + 8) * GPITCH + kc + 8]);
                al[mt][0] = *reinterpret_cast<const uint32_t*>(&sAl[r0 * GPITCH + kc]);
                al[mt][1] = *reinterpret_cast<const uint32_t*>(&sAl[(r0 + 8) * GPITCH + kc]);
                al[mt][2] = *reinterpret_cast<const uint32_t*>(&sAl[r0 * GPITCH + kc + 8]);
                al[mt][3] = *reinterpret_cast<const uint32_t*>(&sAl[(r0 + 8) * GPITCH + kc + 8]);
            }
#pragma unroll
            for (int nt = 0; nt < 8; ++nt) {
                const int n0 = wn * 64 + nt * 8 + g;
                uint32_t bh[2], bl[2];
                bh[0] = *reinterpret_cast<const uint32_t*>(&sBh[n0 * GPITCH + kc]);
                bh[1] = *reinterpret_cast<const uint32_t*>(&sBh[n0 * GPITCH + kc + 8]);
                bl[0] = *reinterpret_cast<const uint32_t*>(&sBl[n0 * GPITCH + kc]);
                bl[1] = *reinterpret_cast<const uint32_t*>(&sBl[n0 * GPITCH + kc + 8]);
#pragma unroll
                for (int mt = 0; mt < 2; ++mt) {
                    mma16816(acc[mt][nt], ah[mt], bh);
                    mma16816(acc[mt][nt], ah[mt], bl);
                    mma16816(acc[mt][nt], al[mt], bh);
                }
            }
        }
        __syncthreads();
    }

    // ---- epilogue ----
    if (MODE == 0) {
#pragma unroll
        for (int mt = 0; mt < 2; ++mt) {
#pragma unroll
            for (int nt = 0; nt < 8; ++nt) {
#pragma unroll
                for (int e = 0; e < 4; ++e) {
                    const int m = bm + wm * 32 + mt * 16 + g + (e >> 1) * 8;
                    const int f = bn + wn * 64 + nt * 8 + tig * 2 + (e & 1);
                    float v = acc[mt][nt][e] + __ldg(&bias[f]);
                    const int ii = f / 3;
                    const int s  = f - ii * 3;
                    const int head = ii >> 6;
                    const int dd   = ii & 63;
                    const int l = m >> 2;
                    const int n = m & 3;
                    const int b = n * H + head;
                    if (s == 0) v *= QSCALE;
                    __nv_bfloat16 h = __float2bfloat16(v);
                    __nv_bfloat16 lo = __float2bfloat16(v - __bfloat162float(h));
                    if (s == 2) {
                        const size_t off = ((size_t)b * DHEAD + dd) * L_SEQ + l;
                        gVthi[off] = h; gVtlo[off] = lo;
                    } else {
                        const size_t off = (((size_t)b * L_SEQ + l) << 6) + dd;
                        if (s == 0) { gQhi[off] = h; gQlo[off] = lo; }
                        else        { gKhi[off] = h; gKlo[off] = lo; }
                    }
                }
            }
        }
    } else {
#pragma unroll
        for (int mt = 0; mt < 2; ++mt) {
#pragma unroll
            for (int nt = 0; nt < 8; ++nt) {
                const int f = bn + wn * 64 + nt * 8 + tig * 2;
                const float b0 = __ldg(&bias[f]);
                const float b1 = __ldg(&bias[f + 1]);
                const int m0 = bm + wm * 32 + mt * 16 + g;
                float2 v0 = make_float2(acc[mt][nt][0] + b0, acc[mt][nt][1] + b1);
                float2 v1 = make_float2(acc[mt][nt][2] + b0, acc[mt][nt][3] + b1);
                *reinterpret_cast<float2*>(outp + (size_t)m0 * EMB + f) = v0;
                *reinterpret_cast<float2*>(outp + (size_t)(m0 + 8) * EMB + f) = v1;
            }
        }
    }
}

// ---------------------------------------------------------------------------
// Tensor-core flash attention (unchanged from round 4).
// ---------------------------------------------------------------------------
#define AP 72
#define AARR (64 * AP)
#define ATTN_SMEM (6 * AARR * 2)   // 55296 bytes

__global__ __launch_bounds__(128) void attn_mma_kernel()
{
    extern __shared__ __nv_bfloat16 asm_[];
    __nv_bfloat16* sQh = asm_;
    __nv_bfloat16* sQl = asm_ + AARR;
    __nv_bfloat16* sKh = asm_ + 2 * AARR;
    __nv_bfloat16* sKl = asm_ + 3 * AARR;
    __nv_bfloat16* sVh = asm_ + 4 * AARR;
    __nv_bfloat16* sVl = asm_ + 5 * AARR;

    const int qt = blockIdx.x;
    const int b  = blockIdx.y;
    const int tid = threadIdx.x;
    const int wid = tid >> 5;
    const int lane = tid & 31;
    const int g   = lane >> 2;
    const int tig = lane & 3;

    {
        const __nv_bfloat16* Qh = gQhi + (((size_t)b * L_SEQ + qt * 64) << 6);
        const __nv_bfloat16* Ql = gQlo + (((size_t)b * L_SEQ + qt * 64) << 6);
#pragma unroll
        for (int u = 0; u < 4; ++u) {
            int i = tid + u * 128;
            int r = i >> 3, cb = (i & 7) * 8;
            *reinterpret_cast<uint4*>(&sQh[r * AP + cb]) =
                *reinterpret_cast<const uint4*>(Qh + r * 64 + cb);
            *reinterpret_cast<uint4*>(&sQl[r * AP + cb]) =
                *reinterpret_cast<const uint4*>(Ql + r * 64 + cb);
        }
    }
    __syncthreads();

    uint32_t qh[4][4], ql[4][4];
    {
        const int r0 = wid * 16 + g;
#pragma unroll
        for (int ks = 0; ks < 4; ++ks) {
            const int kc = ks * 16 + tig * 2;
            qh[ks][0] = *reinterpret_cast<const uint32_t*>(&sQh[r0 * AP + kc]);
            qh[ks][1] = *reinterpret_cast<const uint32_t*>(&sQh[(r0 + 8) * AP + kc]);
            qh[ks][2] = *reinterpret_cast<const uint32_t*>(&sQh[r0 * AP + kc + 8]);
            qh[ks][3] = *reinterpret_cast<const uint32_t*>(&sQh[(r0 + 8) * AP + kc + 8]);
            ql[ks][0] = *reinterpret_cast<const uint32_t*>(&sQl[r0 * AP + kc]);
            ql[ks][1] = *reinterpret_cast<const uint32_t*>(&sQl[(r0 + 8) * AP + kc]);
            ql[ks][2] = *reinterpret_cast<const uint32_t*>(&sQl[r0 * AP + kc + 8]);
            ql[ks][3] = *reinterpret_cast<const uint32_t*>(&sQl[(r0 + 8) * AP + kc + 8]);
        }
    }

    float m0 = -INFINITY, m1 = -INFINITY, l0 = 0.f, l1 = 0.f;
    float o[8][4] = {};

    const __nv_bfloat16* Khb = gKhi + (((size_t)b * L_SEQ) << 6);
    const __nv_bfloat16* Klb = gKlo + (((size_t)b * L_SEQ) << 6);
    const __nv_bfloat16* Vhb = gVthi + (size_t)b * DHEAD * L_SEQ;
    const __nv_bfloat16* Vlb = gVtlo + (size_t)b * DHEAD * L_SEQ;

    for (int kt = 0; kt < L_SEQ / 64; ++kt) {
#pragma unroll
        for (int u = 0; u < 4; ++u) {
            int i = tid + u * 128;
            int r = i >> 3, cb = (i & 7) * 8;
            *reinterpret_cast<uint4*>(&sKh[r * AP + cb]) =
                *reinterpret_cast<const uint4*>(Khb + ((size_t)(kt * 64 + r) << 6) + cb);
            *reinterpret_cast<uint4*>(&sKl[r * AP + cb]) =
                *reinterpret_cast<const uint4*>(Klb + ((size_t)(kt * 64 + r) << 6) + cb);
            *reinterpret_cast<uint4*>(&sVh[r * AP + cb]) =
                *reinterpret_cast<const uint4*>(Vhb + (size_t)r * L_SEQ + kt * 64 + cb);
            *reinterpret_cast<uint4*>(&sVl[r * AP + cb]) =
                *reinterpret_cast<const uint4*>(Vlb + (size_t)r * L_SEQ + kt * 64 + cb);
        }
        __syncthreads();

        float s[8][4] = {};
#pragma unroll
        for (int ks = 0; ks < 4; ++ks) {
            const int kc = ks * 16 + tig * 2;
#pragma unroll
            for (int nt = 0; nt < 8; ++nt) {
                const int n0 = nt * 8 + g;
                uint32_t bh[2], bl[2];
                bh[0] = *reinterpret_cast<const uint32_t*>(&sKh[n0 * AP + kc]);
                bh[1] = *reinterpret_cast<const uint32_t*>(&sKh[n0 * AP + kc + 8]);
                bl[0] = *reinterpret_cast<const uint32_t*>(&sKl[n0 * AP + kc]);
                bl[1] = *reinterpret_cast<const uint32_t*>(&sKl[n0 * AP + kc + 8]);
                mma16816(s[nt], qh[ks], bh);
                mma16816(s[nt], qh[ks], bl);
                mma16816(s[nt], ql[ks], bh);
            }
        }

        float mx0 = -INFINITY, mx1 = -INFINITY;
#pragma unroll
        for (int nt = 0; nt < 8; ++nt) {
            mx0 = fmaxf(mx0, fmaxf(s[nt][0], s[nt][1]));
            mx1 = fmaxf(mx1, fmaxf(s[nt][2], s[nt][3]));
        }
        mx0 = fmaxf(mx0, __shfl_xor_sync(0xffffffffu, mx0, 1));
        mx0 = fmaxf(mx0, __shfl_xor_sync(0xffffffffu, mx0, 2));
        mx1 = fmaxf(mx1, __shfl_xor_sync(0xffffffffu, mx1, 1));
        mx1 = fmaxf(mx1, __shfl_xor_sync(0xffffffffu, mx1, 2));

        const float nm0 = fmaxf(m0, mx0);
        const float nm1 = fmaxf(m1, mx1);
        const float c0 = __expf(m0 - nm0);
        const float c1 = __expf(m1 - nm1);
        m0 = nm0; m1 = nm1;

        float rs0 = 0.f, rs1 = 0.f;
        uint32_t ph[4][4], pl[4][4];
#pragma unroll
        for (int nt = 0; nt < 8; ++nt) {
            float p0 = __expf(s[nt][0] - nm0);
            float p1 = __expf(s[nt][1] - nm0);
            float p2 = __expf(s[nt][2] - nm1);
            float p3 = __expf(s[nt][3] - nm1);
            rs0 += p0 + p1;
            rs1 += p2 + p3;
            float h0 = bf16_hi_part(p0), h1 = bf16_hi_part(p1);
            float h2 = bf16_hi_part(p2), h3 = bf16_hi_part(p3);
            const int ks2 = nt >> 1;
            const int half = (nt & 1) * 2;
            ph[ks2][half + 0] = pack_bf16x2(h0, h1);
            ph[ks2][half + 1] = pack_bf16x2(h2, h3);
            pl[ks2][half + 0] = pack_bf16x2(p0 - h0, p1 - h1);
            pl[ks2][half + 1] = pack_bf16x2(p2 - h2, p3 - h3);
        }
        rs0 += __shfl_xor_sync(0xffffffffu, rs0, 1);
        rs0 += __shfl_xor_sync(0xffffffffu, rs0, 2);
        rs1 += __shfl_xor_sync(0xffffffffu, rs1, 1);
        rs1 += __shfl_xor_sync(0xffffffffu, rs1, 2);
        l0 = l0 * c0 + rs0;
        l1 = l1 * c1 + rs1;

#pragma unroll
        for (int nt = 0; nt < 8; ++nt) {
            o[nt][0] *= c0; o[nt][1] *= c0;
            o[nt][2] *= c1; o[nt][3] *= c1;
        }

#pragma unroll
        for (int ks2 = 0; ks2 < 4; ++ks2) {
            const int kc = ks2 * 16 + tig * 2;
#pragma unroll
            for (int nt = 0; nt < 8; ++nt) {
                const int n0 = nt * 8 + g;
                uint32_t bh[2], bl[2];
                bh[0] = *reinterpret_cast<const uint32_t*>(&sVh[n0 * AP + kc]);
                bh[1] = *reinterpret_cast<const uint32_t*>(&sVh[n0 * AP + kc + 8]);
                bl[0] = *reinterpret_cast<const uint32_t*>(&sVl[n0 * AP + kc]);
                bl[1] = *reinterpret_cast<const uint32_t*>(&sVl[n0 * AP + kc + 8]);
                mma16816(o[nt], ph[ks2], bh);
                mma16816(o[nt], pl[ks2], bh);
                mma16816(o[nt], ph[ks2], bl);
            }
        }
        __syncthreads();
    }

    const float inv0 = 1.0f / l0;
    const float inv1 = 1.0f / l1;
    const int n    = b >> 4;
    const int head = b & 15;
    const int lg0 = qt * 64 + wid * 16 + g;
    const int lg1 = lg0 + 8;
#pragma unroll
    for (int nt = 0; nt < 8; ++nt) {
        const int dd = nt * 8 + tig * 2;
        const size_t base0 = ((size_t)lg0 * NB + n) * INNER + head * DHEAD + dd;
        const size_t base1 = ((size_t)lg1 * NB + n) * INNER + head * DHEAD + dd;
        float v0 = o[nt][0] * inv0, v1 = o[nt][1] * inv0;
        float v2 = o[nt][2] * inv1, v3 = o[nt][3] * inv1;
        float h0 = bf16_hi_part(v0), h1 = bf16_hi_part(v1);
        float h2 = bf16_hi_part(v2), h3 = bf16_hi_part(v3);
        *reinterpret_cast<uint32_t*>(&gOhi[base0]) = pack_bf16x2(h0, h1);
        *reinterpret_cast<uint32_t*>(&gOlo[base0]) = pack_bf16x2(v0 - h0, v1 - h1);
        *reinterpret_cast<uint32_t*>(&gOhi[base1]) = pack_bf16x2(h2, h3);
        *reinterpret_cast<uint32_t*>(&gOlo[base1]) = pack_bf16x2(v2 - h2, v3 - h3);
    }
}

// ---------------------------------------------------------------------------
// Launcher
// ---------------------------------------------------------------------------
extern "C" void kernel_launch(void* const* d_in, const int* in_sizes, int n_in,
                              void* d_out, int out_size)
{
    const float* query    = (const float*)d_in[0];
    const float* qkv_proj = (const float*)d_in[1];
    const float* qkv_bias = (const float*)d_in[2];
    const float* out_proj = (const float*)d_in[3];
    const float* out_bias = (const float*)d_in[4];
    float* out = (float*)d_out;

    static bool init_done = false;
    if (!init_done) {
        cudaFuncSetAttribute(attn_mma_kernel,
                             cudaFuncAttributeMaxDynamicSharedMemorySize, ATTN_SMEM);
        cudaFuncSetAttribute(mma_gemm<0>,
                             cudaFuncAttributeMaxDynamicSharedMemorySize, GEMM_SMEM);
        cudaFuncSetAttribute(mma_gemm<1>,
                             cudaFuncAttributeMaxDynamicSharedMemorySize, GEMM_SMEM);
        init_done = true;
    }

    convert_kernel<0><<<1184, 256>>>(query,    (M_ROWS * EMB) / 4);
    convert_kernel<1><<<1184, 256>>>(qkv_proj, (3 * INNER * EMB) / 4);
    convert_kernel<2><<<592, 256>>>(out_proj,  (EMB * INNER) / 4);

    dim3 g1(M_ROWS / 128, (3 * INNER) / 128);
    mma_gemm<0><<<g1, 256, GEMM_SMEM>>>(qkv_bias, nullptr);

    dim3 g2(L_SEQ / 64, BATCH);
    attn_mma_kernel<<<g2, 128, ATTN_SMEM>>>();

    dim3 g3(M_ROWS / 128, EMB / 128);
    mma_gemm<1><<<g3, 256, GEMM_SMEM>>>(out_bias, out);
}